// round 16
// baseline (speedup 1.0000x reference)
#include <cuda_runtime.h>
#include <cuda_fp16.h>
#include <math.h>
#include <stdint.h>

// Problem constants
#define BSZ 2
#define HN  16
#define SQ  2048
#define DH  64
#define EMB 1024
#define BH  (BSZ*HN)

// Scratch (device globals; no allocations allowed)
__device__ uint32_t g_Qh16[(size_t)BH * SQ * DH / 2];  // fp16x2, pre-scaled by 0.125*log2(e)
__device__ uint32_t g_Kh16[(size_t)BH * SQ * DH / 2];
__device__ uint32_t g_Vh16[(size_t)BH * SQ * DH / 2];
__device__ uint32_t g_X16[(size_t)3 * BSZ * SQ * EMB / 2];  // fp16 q,k,v inputs
__device__ uint32_t g_W16[(size_t)4 * EMB * EMB / 2];       // fp16 Wq,Wk,Wv,Wo
__device__ uint32_t g_ctx16[(size_t)BSZ * SQ * EMB / 2];    // fp16 ctx from fused_attn
__device__ float    g_attn_fb[(size_t)BH * SQ * SQ];        // fallback attn

#define XSEG ((size_t)BSZ * SQ * EMB / 2)
#define WSEG ((size_t)EMB * EMB / 2)

// ===========================================================================
// helpers
// ===========================================================================
__device__ __forceinline__ uint32_t f2h2(float lo, float hi) {
    uint32_t r;
    asm("cvt.rn.f16x2.f32 %0, %1, %2;" : "=r"(r) : "f"(hi), "f"(lo));
    return r;
}
__device__ __forceinline__ float ex2f(float x) {  // 2^x; ex2(-inf) = +0
    float r;
    asm("ex2.approx.f32 %0, %1;" : "=f"(r) : "f"(x));
    return r;
}
__device__ __forceinline__ uint32_t smem_u32(const void* p) {
    uint32_t a;
    asm("{ .reg .u64 t; cvta.to.shared.u64 t, %1; cvt.u32.u64 %0, t; }" : "=r"(a) : "l"(p));
    return a;
}

#define MMA_F16(c, A0, A1, A2, A3, B0, B1)                                       \
    asm volatile("mma.sync.aligned.m16n8k16.row.col.f32.f16.f16.f32 "            \
                 "{%0,%1,%2,%3},{%4,%5,%6,%7},{%8,%9},{%0,%1,%2,%3};"            \
                 : "+f"((c)[0]), "+f"((c)[1]), "+f"((c)[2]), "+f"((c)[3])        \
                 : "r"(A0), "r"(A1), "r"(A2), "r"(A3), "r"(B0), "r"(B1))

#define LDSM_X4(r0, r1, r2, r3, saddr)                                           \
    asm volatile("ldmatrix.sync.aligned.m8n8.x4.shared.b16 {%0,%1,%2,%3}, [%4];" \
                 : "=r"(r0), "=r"(r1), "=r"(r2), "=r"(r3) : "r"(saddr))

#define LDSM_X4_T(r0, r1, r2, r3, saddr)                                         \
    asm volatile("ldmatrix.sync.aligned.m8n8.x4.trans.shared.b16 {%0,%1,%2,%3}, [%4];" \
                 : "=r"(r0), "=r"(r1), "=r"(r2), "=r"(r3) : "r"(saddr))

#define CP_ASYNC16(saddr, gptr) \
    asm volatile("cp.async.cg.shared.global [%0], [%1], 16;" :: "r"(saddr), "l"(gptr))
#define CP_COMMIT() asm volatile("cp.async.commit_group;")
#define CP_WAIT0()  asm volatile("cp.async.wait_group 0;")
#define CP_WAIT1()  asm volatile("cp.async.wait_group 1;")

// ===========================================================================
// fp32 -> fp16 conversion of inputs & weights. grid (4096, 7).
// Rounding identical to the per-use cvt the GEMM loaders previously applied.
// ===========================================================================
__global__ void __launch_bounds__(256) convert_fp16(
    const float* __restrict__ xq, const float* __restrict__ xk,
    const float* __restrict__ xv, const float* __restrict__ wq,
    const float* __restrict__ wk, const float* __restrict__ wv,
    const float* __restrict__ wo)
{
    const int z = blockIdx.y;
    const float* src;
    uint32_t* dst;
    size_t n4;
    if (z < 3) {
        src = (z == 0) ? xq : (z == 1) ? xk : xv;
        dst = g_X16 + (size_t)z * XSEG;
        n4 = (size_t)BSZ * SQ * EMB / 4;
    } else {
        src = (z == 3) ? wq : (z == 4) ? wk : (z == 5) ? wv : wo;
        dst = g_W16 + (size_t)(z - 3) * WSEG;
        n4 = (size_t)EMB * EMB / 4;
    }
    const size_t idx = (size_t)blockIdx.x * 256 + threadIdx.x;
    if (idx < n4) {
        const float4 v = ((const float4*)src)[idx];
        ((uint2*)dst)[idx] = make_uint2(f2h2(v.x, v.y), f2h2(v.z, v.w));
    }
}

// ===========================================================================
// fp16-operand GEMM, R12/R15 pipeline structure preserved:
// register-prefetch LDG.128 (fp16 payload) -> STS.128 -> ldmatrix -> MMA.
// MODE 0: C fp32 [m][EMB] (final output). MODE 1: Q proj scaled by
// 0.125*log2(e). MODE 2/3: K/V. MODE 1/2/3 scatter fp16x2 to [B,H,S,D].
// ===========================================================================
#define GLD 20   // smem row stride in u32 (16 payload + 4 pad); ldmatrix conflict-free

template<int MODE>
__device__ __forceinline__ void gemm16_body(const uint32_t* __restrict__ A16,
                                            const uint32_t* __restrict__ B16,
                                            const float* __restrict__ bias,
                                            float* __restrict__ C,
                                            uint32_t* As, uint32_t* Bs,
                                            int m0, int n0)
{
    constexpr int KU  = EMB / 2;   // u32 per gmem row
    constexpr int NKB = EMB / 32;  // 32 k-blocks

    const int tid  = threadIdx.x;
    const int wid  = tid >> 5, lane = tid & 31;
    const int g    = lane >> 2, t = lane & 3;
    const int wm   = (wid & 3) * 32;
    const int wn   = (wid >> 2) * 64;

    const uint32_t AsA = smem_u32(As);
    const uint32_t BsA = smem_u32(Bs);
    const int lm_r = ((lane >> 3) & 1) * 8 + (lane & 7);
    const int lm_c = (lane >> 4) * 4;

    // loader: 4 threads per row (uint4 each), rows lrow and lrow+64
    const int lrow = tid >> 2;
    const int lc   = tid & 3;
    const uint32_t* pA = A16 + (size_t)(m0 + lrow) * KU + lc * 4;
    const uint32_t* pB = B16 + (size_t)(n0 + lrow) * KU + lc * 4;

    float acc[2][8][4];
#pragma unroll
    for (int i = 0; i < 2; i++)
#pragma unroll
        for (int j = 0; j < 8; j++)
#pragma unroll
            for (int l = 0; l < 4; l++) acc[i][j][l] = 0.f;

    uint4 ra[2], rb[2];
#pragma unroll
    for (int i = 0; i < 2; i++) {
        ra[i] = *(const uint4*)(pA + (size_t)(64 * i) * KU);
        rb[i] = *(const uint4*)(pB + (size_t)(64 * i) * KU);
    }

    for (int kb = 0; kb < NKB; kb++) {
#pragma unroll
        for (int i = 0; i < 2; i++) {
            *(uint4*)&As[(lrow + 64 * i) * GLD + lc * 4] = ra[i];
            *(uint4*)&Bs[(lrow + 64 * i) * GLD + lc * 4] = rb[i];
        }
        __syncthreads();

        if (kb + 1 < NKB) {
#pragma unroll
            for (int i = 0; i < 2; i++) {
                ra[i] = *(const uint4*)(pA + (size_t)(64 * i) * KU + (kb + 1) * 16);
                rb[i] = *(const uint4*)(pB + (size_t)(64 * i) * KU + (kb + 1) * 16);
            }
        }

#pragma unroll
        for (int kt = 0; kt < 2; kt++) {
            const int kq = kt * 8;
            uint32_t af[2][4];
#pragma unroll
            for (int mt = 0; mt < 2; mt++)
                LDSM_X4(af[mt][0], af[mt][1], af[mt][2], af[mt][3],
                        AsA + 4 * ((wm + mt * 16 + lm_r) * GLD + kq + lm_c));
            uint32_t bf[8][2];
#pragma unroll
            for (int p = 0; p < 4; p++) {
                uint32_t r0, r1, r2, r3;
                LDSM_X4(r0, r1, r2, r3,
                        BsA + 4 * ((wn + p * 16 + lm_r) * GLD + kq + lm_c));
                bf[2 * p][0] = r0; bf[2 * p + 1][0] = r1;
                bf[2 * p][1] = r2; bf[2 * p + 1][1] = r3;
            }
#pragma unroll
            for (int nt = 0; nt < 8; nt++)
#pragma unroll
                for (int mt = 0; mt < 2; mt++)
                    MMA_F16(acc[mt][nt], af[mt][0], af[mt][1], af[mt][2], af[mt][3],
                            bf[nt][0], bf[nt][1]);
        }
        __syncthreads();
    }

    // Q projection folds 0.125 * log2(e): scores become ex2-ready exponents
    const float osc = (MODE == 1) ? 0.125f * 1.4426950408889634f : 1.0f;
#pragma unroll
    for (int nt = 0; nt < 8; nt++) {
        const int n = n0 + wn + nt * 8 + 2 * t;
        const float b0 = bias[n], b1 = bias[n + 1];
#pragma unroll
        for (int mt = 0; mt < 2; mt++) {
            const int mlo = m0 + wm + mt * 16 + g;
            const int mhi = mlo + 8;
            const float v00 = (acc[mt][nt][0] + b0) * osc, v01 = (acc[mt][nt][1] + b1) * osc;
            const float v10 = (acc[mt][nt][2] + b0) * osc, v11 = (acc[mt][nt][3] + b1) * osc;
            if (MODE == 0) {
                *(float2*)(C + (size_t)mlo * EMB + n) = make_float2(v00, v01);
                *(float2*)(C + (size_t)mhi * EMB + n) = make_float2(v10, v11);
            } else {
                const int h = n >> 6, dd = n & 63;
                uint32_t* dst = (MODE == 1) ? g_Qh16 : (MODE == 2 ? g_Kh16 : g_Vh16);
                const int blo = mlo / SQ, slo = mlo % SQ;
                const int bhi = mhi / SQ, shi = mhi % SQ;
                dst[((size_t)(blo * HN + h) * SQ + slo) * 32 + (dd >> 1)] = f2h2(v00, v01);
                dst[((size_t)(bhi * HN + h) * SQ + shi) * 32 + (dd >> 1)] = f2h2(v10, v11);
            }
        }
    }
}

// Fused QKV projection: blockIdx.z selects {Q,K,V}. One launch, 768 CTAs.
__global__ void __launch_bounds__(256, 2) qkv_mma(const float* __restrict__ bq,
                                                  const float* __restrict__ bk,
                                                  const float* __restrict__ bv)
{
    __shared__ uint32_t As[128 * GLD];
    __shared__ uint32_t Bs[128 * GLD];
    const int m0 = blockIdx.y * 128, n0 = blockIdx.x * 128;
    const int z = blockIdx.z;
    const uint32_t* A16 = g_X16 + (size_t)z * XSEG;
    const uint32_t* B16 = g_W16 + (size_t)z * WSEG;
    if (z == 0)      gemm16_body<1>(A16, B16, bq, nullptr, As, Bs, m0, n0);
    else if (z == 1) gemm16_body<2>(A16, B16, bk, nullptr, As, Bs, m0, n0);
    else             gemm16_body<3>(A16, B16, bv, nullptr, As, Bs, m0, n0);
}

// Output projection: A = g_ctx16 (fp16 from fused_attn), B = Wo fp16.
__global__ void __launch_bounds__(256, 2) oproj_mma(const float* __restrict__ bias,
                                                    float* __restrict__ C)
{
    __shared__ uint32_t As[128 * GLD];
    __shared__ uint32_t Bs[128 * GLD];
    gemm16_body<0>(g_ctx16, g_W16 + 3 * WSEG, bias, C, As, Bs,
                   blockIdx.y * 128, blockIdx.x * 128);
}

// ===========================================================================
// Fully fused attention (R15 structure): scores + no-max softmax + PV.
// Q pre-scaled by 0.125*log2(e) -> exp via bare ex2.approx.f32.
// Diag-tile jj-skip in both passes. Pass 0: 3-stage K ring, one sync/kb.
// Pass 1: 2-stage K+V. O written as fp16 (same rounding oproj applied).
// ===========================================================================
#define FS_LD  36
#define FS_TILE (128 * FS_LD)
#define FUSED_SMEM (5 * FS_TILE * 4)  // Q + 2xK + 2xV = 92160 B

__global__ void __launch_bounds__(256, 2) fused_attn(float* __restrict__ attn)
{
    const int bh = blockIdx.y;
    const int b = bh >> 4, h = bh & 15;
    const int bm = (int)gridDim.x - 1 - (int)blockIdx.x;  // heavy tiles first
    float* out = attn + (size_t)bh * SQ * SQ;
    const uint32_t* Q16 = g_Qh16 + (size_t)bh * SQ * 32;
    const uint32_t* K16 = g_Kh16 + (size_t)bh * SQ * 32;
    const uint32_t* V16 = g_Vh16 + (size_t)bh * SQ * 32;

    extern __shared__ __align__(16) uint32_t dyn_smem[];
    const uint32_t QsA = smem_u32(dyn_smem);
    const uint32_t KsA = QsA + FS_TILE * 4;
    const uint32_t VsA = QsA + 3 * FS_TILE * 4;

    const int tid = threadIdx.x;
    const int wid = tid >> 5, lane = tid & 31;
    const int g = lane >> 2, t = lane & 3;
    const int wm = wid * 16;
    const int lm_r = ((lane >> 3) & 1) * 8 + (lane & 7);
    const int lm_c = (lane >> 4) * 4;
    const int lm_v = lane >> 4;

    const int lrow = tid >> 3;
    const int lc4  = tid & 7;

    auto kstage = [&](int s) -> uint32_t {
        return (s < 2) ? (KsA + (uint32_t)s * FS_TILE * 4) : VsA;
    };

    // ---- prologue: Q tile, K0, K1 ----
#pragma unroll
    for (int i = 0; i < 4; i++) {
        const int row = lrow + 32 * i;
        CP_ASYNC16(QsA + (row * FS_LD + lc4 * 4) * 4,
                   Q16 + (size_t)(bm * 128 + row) * 32 + lc4 * 4);
    }
    CP_COMMIT();
#pragma unroll
    for (int i = 0; i < 4; i++) {
        const int row = lrow + 32 * i;
        CP_ASYNC16(kstage(0) + (row * FS_LD + lc4 * 4) * 4,
                   K16 + (size_t)row * 32 + lc4 * 4);
    }
    CP_COMMIT();
    if (bm >= 1) {
#pragma unroll
        for (int i = 0; i < 4; i++) {
            const int row = lrow + 32 * i;
            CP_ASYNC16(kstage(1) + (row * FS_LD + lc4 * 4) * 4,
                       K16 + (size_t)(128 + row) * 32 + lc4 * 4);
        }
        CP_COMMIT();
    }

    const int R0 = bm * 128 + wm + g;
    const int R1 = R0 + 8;

    uint32_t af[4][4];

    // ================= Pass 0: row sums of 2^y, single sync per kb ======
    float s0 = 0.f, s1 = 0.f;

    for (int kb = 0; kb <= bm; kb++) {
        if (kb < bm) { CP_WAIT1(); } else { CP_WAIT0(); }
        __syncthreads();

        if (kb == 0) {
#pragma unroll
            for (int kt = 0; kt < 4; kt++)
                LDSM_X4(af[kt][0], af[kt][1], af[kt][2], af[kt][3],
                        QsA + 4 * ((wm + lm_r) * FS_LD + kt * 8 + lm_c));
        }

        const uint32_t KsbA = kstage(kb % 3);
        const bool diag = (kb == bm);
        const int jjmax = diag ? (wid + 1) : 8;
#pragma unroll
        for (int jj = 0; jj < 8; jj++) {
            if (jj >= jjmax) break;
            float p0[4] = {0.f, 0.f, 0.f, 0.f};
            float p1[4] = {0.f, 0.f, 0.f, 0.f};
#pragma unroll
            for (int kt = 0; kt < 4; kt++) {
                uint32_t r0, r1, r2, r3;
                LDSM_X4(r0, r1, r2, r3,
                        KsbA + 4 * ((jj * 16 + lm_r) * FS_LD + kt * 8 + lm_c));
                MMA_F16(p0, af[kt][0], af[kt][1], af[kt][2], af[kt][3], r0, r2);
                MMA_F16(p1, af[kt][0], af[kt][1], af[kt][2], af[kt][3], r1, r3);
            }
            float x00 = p0[0], x01 = p0[1];
            float x10 = p1[0], x11 = p1[1];
            float x02 = p0[2], x03 = p0[3];
            float x12 = p1[2], x13 = p1[3];
            if (diag) {
                const int c = kb * 128 + jj * 16 + 2 * t;
                if (c     > R0) x00 = -INFINITY;
                if (c + 1 > R0) x01 = -INFINITY;
                if (c + 8 > R0) x10 = -INFINITY;
                if (c + 9 > R0) x11 = -INFINITY;
                if (c     > R1) x02 = -INFINITY;
                if (c + 1 > R1) x03 = -INFINITY;
                if (c + 8 > R1) x12 = -INFINITY;
                if (c + 9 > R1) x13 = -INFINITY;
            }
            s0 += ex2f(x00) + ex2f(x01) + ex2f(x10) + ex2f(x11);
            s1 += ex2f(x02) + ex2f(x03) + ex2f(x12) + ex2f(x13);
        }

        if (kb + 2 <= bm) {
            const uint32_t dstA = kstage((kb + 2) % 3);
#pragma unroll
            for (int i = 0; i < 4; i++) {
                const int row = lrow + 32 * i;
                CP_ASYNC16(dstA + (row * FS_LD + lc4 * 4) * 4,
                           K16 + (size_t)((kb + 2) * 128 + row) * 32 + lc4 * 4);
            }
            CP_COMMIT();
        }
    }
    __syncthreads();  // protect pass-1 prologue writes

    s0 += __shfl_xor_sync(0xffffffffu, s0, 1);
    s0 += __shfl_xor_sync(0xffffffffu, s0, 2);
    s1 += __shfl_xor_sync(0xffffffffu, s1, 1);
    s1 += __shfl_xor_sync(0xffffffffu, s1, 2);
    const float inv0 = 1.f / s0;
    const float inv1 = 1.f / s1;

    // ================= Pass 1: recompute + write attn + O accum =========
    float o_acc[8][4];
#pragma unroll
    for (int dt = 0; dt < 8; dt++)
#pragma unroll
        for (int l = 0; l < 4; l++) o_acc[dt][l] = 0.f;

    float* rowlo = out + (size_t)R0 * SQ;
    float* rowhi = out + (size_t)R1 * SQ;

#pragma unroll
    for (int i = 0; i < 4; i++) {
        const int row = lrow + 32 * i;
        CP_ASYNC16(KsA + (row * FS_LD + lc4 * 4) * 4,
                   K16 + (size_t)row * 32 + lc4 * 4);
        CP_ASYNC16(VsA + (row * FS_LD + lc4 * 4) * 4,
                   V16 + (size_t)row * 32 + lc4 * 4);
    }
    CP_COMMIT();

    for (int kb = 0; kb <= bm; kb++) {
        if (kb < bm) {
            const uint32_t dstK = KsA + ((kb + 1) & 1) * FS_TILE * 4;
            const uint32_t dstV = VsA + ((kb + 1) & 1) * FS_TILE * 4;
#pragma unroll
            for (int i = 0; i < 4; i++) {
                const int row = lrow + 32 * i;
                CP_ASYNC16(dstK + (row * FS_LD + lc4 * 4) * 4,
                           K16 + (size_t)((kb + 1) * 128 + row) * 32 + lc4 * 4);
                CP_ASYNC16(dstV + (row * FS_LD + lc4 * 4) * 4,
                           V16 + (size_t)((kb + 1) * 128 + row) * 32 + lc4 * 4);
            }
            CP_COMMIT();
            CP_WAIT1();
        } else {
            CP_WAIT0();
        }
        __syncthreads();

        const uint32_t KsbA = KsA + (kb & 1) * FS_TILE * 4;
        const uint32_t VsbA = VsA + (kb & 1) * FS_TILE * 4;
        const bool diag = (kb == bm);
        const int jjmax = diag ? (wid + 1) : 8;
#pragma unroll
        for (int jj = 0; jj < 8; jj++) {
            if (jj >= jjmax) break;
            float p0[4] = {0.f, 0.f, 0.f, 0.f};
            float p1[4] = {0.f, 0.f, 0.f, 0.f};
#pragma unroll
            for (int kt = 0; kt < 4; kt++) {
                uint32_t r0, r1, r2, r3;
                LDSM_X4(r0, r1, r2, r3,
                        KsbA + 4 * ((jj * 16 + lm_r) * FS_LD + kt * 8 + lm_c));
                MMA_F16(p0, af[kt][0], af[kt][1], af[kt][2], af[kt][3], r0, r2);
                MMA_F16(p1, af[kt][0], af[kt][1], af[kt][2], af[kt][3], r1, r3);
            }
            float x00 = p0[0], x01 = p0[1];
            float x10 = p1[0], x11 = p1[1];
            float x02 = p0[2], x03 = p0[3];
            float x12 = p1[2], x13 = p1[3];
            const int c = kb * 128 + jj * 16 + 2 * t;
            if (diag) {
                if (c     > R0) x00 = -INFINITY;
                if (c + 1 > R0) x01 = -INFINITY;
                if (c + 8 > R0) x10 = -INFINITY;
                if (c + 9 > R0) x11 = -INFINITY;
                if (c     > R1) x02 = -INFINITY;
                if (c + 1 > R1) x03 = -INFINITY;
                if (c + 8 > R1) x12 = -INFINITY;
                if (c + 9 > R1) x13 = -INFINITY;
            }
            const float e00 = ex2f(x00) * inv0;  // masked -> exact 0
            const float e01 = ex2f(x01) * inv0;
            const float e10 = ex2f(x10) * inv0;
            const float e11 = ex2f(x11) * inv0;
            const float e02 = ex2f(x02) * inv1;
            const float e03 = ex2f(x03) * inv1;
            const float e12 = ex2f(x12) * inv1;
            const float e13 = ex2f(x13) * inv1;

            *(float2*)(rowlo + c)     = make_float2(e00, e01);
            *(float2*)(rowlo + c + 8) = make_float2(e10, e11);
            *(float2*)(rowhi + c)     = make_float2(e02, e03);
            *(float2*)(rowhi + c + 8) = make_float2(e12, e13);

            const uint32_t pa0 = f2h2(e00, e01);
            const uint32_t pa1 = f2h2(e02, e03);
            const uint32_t pa2 = f2h2(e10, e11);
            const uint32_t pa3 = f2h2(e12, e13);
#pragma unroll
            for (int p = 0; p < 4; p++) {
                uint32_t r0, r1, r2, r3;
                LDSM_X4_T(r0, r1, r2, r3,
                          VsbA + 4 * ((jj * 16 + lm_r) * FS_LD + (2 * p + lm_v) * 4));
                MMA_F16(o_acc[2 * p],     pa0, pa1, pa2, pa3, r0, r1);
                MMA_F16(o_acc[2 * p + 1], pa0, pa1, pa2, pa3, r2, r3);
            }
        }

        if (diag) {  // zero-fill skipped strips
            for (int jj = jjmax; jj < 8; jj++) {
                const int c = kb * 128 + jj * 16 + 2 * t;
                *(float2*)(rowlo + c)     = make_float2(0.f, 0.f);
                *(float2*)(rowlo + c + 8) = make_float2(0.f, 0.f);
                *(float2*)(rowhi + c)     = make_float2(0.f, 0.f);
                *(float2*)(rowhi + c + 8) = make_float2(0.f, 0.f);
            }
        }
        __syncthreads();
    }

    // ---- O epilogue: fp16 ctx (same rounding oproj's loader applied) ----
    uint32_t* olo = g_ctx16 + ((size_t)(b * SQ + R0)) * (EMB / 2) + (h * DH) / 2;
    uint32_t* ohi = g_ctx16 + ((size_t)(b * SQ + R1)) * (EMB / 2) + (h * DH) / 2;
#pragma unroll
    for (int dt = 0; dt < 8; dt++) {
        olo[dt * 4 + t] = f2h2(o_acc[dt][0], o_acc[dt][1]);
        ohi[dt * 4 + t] = f2h2(o_acc[dt][2], o_acc[dt][3]);
    }

    // ---- zero-fill upper triangle beyond the diag tile ----
    const int cstart = (bm + 1) * 128;
    const int nc4 = (SQ - cstart) >> 2;
    for (int idx = tid; idx < 128 * nc4; idx += 256) {
        const int r = idx / nc4, cc = idx - r * nc4;
        *(float4*)(out + (size_t)(bm * 128 + r) * SQ + cstart + cc * 4) =
            make_float4(0.f, 0.f, 0.f, 0.f);
    }
}

// ---------------------------------------------------------------------------
extern "C" void kernel_launch(void* const* d_in, const int* in_sizes, int n_in,
                              void* d_out, int out_size)
{
    const float* query = (const float*)d_in[0];
    const float* key_  = (const float*)d_in[1];
    const float* value = (const float*)d_in[2];
    const float* Wq = (const float*)d_in[3];
    const float* bq = (const float*)d_in[4];
    const float* Wk = (const float*)d_in[5];
    const float* bk = (const float*)d_in[6];
    const float* Wv = (const float*)d_in[7];
    const float* bv = (const float*)d_in[8];
    const float* Wo = (const float*)d_in[9];
    const float* bo = (const float*)d_in[10];

    const long long OUT_E = (long long)BSZ * SQ * EMB;
    const long long ATT_E = (long long)BH * SQ * SQ;

    float* outp = (float*)d_out;
    float* attn;
    if ((long long)out_size >= OUT_E + ATT_E) {
        attn = outp + OUT_E;
    } else {
        void* p = nullptr;
        cudaGetSymbolAddress(&p, g_attn_fb);
        attn = (float*)p;
    }

    cudaFuncSetAttribute(fused_attn, cudaFuncAttributeMaxDynamicSharedMemorySize,
                         FUSED_SMEM);

    dim3 gcv((BSZ * SQ * EMB / 4 + 255) / 256, 7);  // (4096, 7)
    convert_fp16<<<gcv, 256>>>(query, key_, value, Wq, Wk, Wv, Wo);

    dim3 gqkv(EMB / 128, (BSZ * SQ) / 128, 3);  // (8, 32, 3) = 768 CTAs
    qkv_mma<<<gqkv, 256>>>(bq, bk, bv);

    dim3 gfs(SQ / 128, BH);                     // (16, 32)
    fused_attn<<<gfs, 256, FUSED_SMEM>>>(attn);

    dim3 gout(EMB / 128, (BSZ * SQ) / 128);     // (8, 32)
    oproj_mma<<<gout, 256>>>(bo, outp);
}

// round 17
// speedup vs baseline: 1.0580x; 1.0580x over previous
#include <cuda_runtime.h>
#include <cuda_fp16.h>
#include <math.h>
#include <stdint.h>

// Problem constants
#define BSZ 2
#define HN  16
#define SQ  2048
#define DH  64
#define EMB 1024
#define BH  (BSZ*HN)

// Scratch (device globals; no allocations allowed)
__device__ uint32_t g_Qh16[(size_t)BH * SQ * DH / 2];  // fp16x2, pre-scaled by 0.125*log2(e)
__device__ uint32_t g_Kh16[(size_t)BH * SQ * DH / 2];
__device__ uint32_t g_Vh16[(size_t)BH * SQ * DH / 2];
__device__ float    g_ctx[(size_t)BSZ * SQ * EMB];     // [B,S,E]
__device__ float    g_attn_fb[(size_t)BH * SQ * SQ];   // fallback attn

// ===========================================================================
// helpers
// ===========================================================================
__device__ __forceinline__ uint32_t f2h2(float lo, float hi) {
    uint32_t r;
    asm("cvt.rn.f16x2.f32 %0, %1, %2;" : "=r"(r) : "f"(hi), "f"(lo));
    return r;
}
__device__ __forceinline__ float ex2f(float x) {  // 2^x; ex2(-inf) = +0
    float r;
    asm("ex2.approx.f32 %0, %1;" : "=f"(r) : "f"(x));
    return r;
}
__device__ __forceinline__ uint32_t smem_u32(const void* p) {
    uint32_t a;
    asm("{ .reg .u64 t; cvta.to.shared.u64 t, %1; cvt.u32.u64 %0, t; }" : "=r"(a) : "l"(p));
    return a;
}
// streaming stores (evict-first): attn is write-once, never re-read
__device__ __forceinline__ void stg_cs_v2(float* p, float x, float y) {
    asm volatile("st.global.cs.v2.f32 [%0], {%1, %2};" :: "l"(p), "f"(x), "f"(y) : "memory");
}
__device__ __forceinline__ void stg_cs_v4_zero(float* p) {
    asm volatile("st.global.cs.v4.f32 [%0], {%1, %1, %1, %1};" :: "l"(p), "f"(0.f) : "memory");
}

#define MMA_F16(c, A0, A1, A2, A3, B0, B1)                                       \
    asm volatile("mma.sync.aligned.m16n8k16.row.col.f32.f16.f16.f32 "            \
                 "{%0,%1,%2,%3},{%4,%5,%6,%7},{%8,%9},{%0,%1,%2,%3};"            \
                 : "+f"((c)[0]), "+f"((c)[1]), "+f"((c)[2]), "+f"((c)[3])        \
                 : "r"(A0), "r"(A1), "r"(A2), "r"(A3), "r"(B0), "r"(B1))

#define LDSM_X4(r0, r1, r2, r3, saddr)                                           \
    asm volatile("ldmatrix.sync.aligned.m8n8.x4.shared.b16 {%0,%1,%2,%3}, [%4];" \
                 : "=r"(r0), "=r"(r1), "=r"(r2), "=r"(r3) : "r"(saddr))

#define LDSM_X4_T(r0, r1, r2, r3, saddr)                                         \
    asm volatile("ldmatrix.sync.aligned.m8n8.x4.trans.shared.b16 {%0,%1,%2,%3}, [%4];" \
                 : "=r"(r0), "=r"(r1), "=r"(r2), "=r"(r3) : "r"(saddr))

#define CP_ASYNC16(saddr, gptr) \
    asm volatile("cp.async.cg.shared.global [%0], [%1], 16;" :: "r"(saddr), "l"(gptr))
#define CP_COMMIT() asm volatile("cp.async.commit_group;")
#define CP_WAIT0()  asm volatile("cp.async.wait_group 0;")
#define CP_WAIT1()  asm volatile("cp.async.wait_group 1;")

// ===========================================================================
// GEMM core body (R12/R15 structure — fp32 LDG register-prefetch, 8 loads in
// flight, cvt + STS, ldmatrix fragments; GLD=20 conflict-free).
// MODE 0: A := g_ctx (fp32 in), C fp32 [m][n]  (output projection)
// MODE 1: Q projection, outputs scaled by 0.125*log2(e) (ex2-ready scores)
// MODE 2/3: K/V projections. MODE 1/2/3 scatter fp16x2 to [B,H,S,D].
// ===========================================================================
#define GLD 20

template<int MODE>
__device__ __forceinline__ void gemm_body(const float* __restrict__ Ap,
                                          const float* __restrict__ W,
                                          const float* __restrict__ bias,
                                          float* __restrict__ C,
                                          uint32_t* As, uint32_t* Bs,
                                          int m0, int n0)
{
    constexpr int K = EMB;
    const int tid  = threadIdx.x;
    const int wid  = tid >> 5, lane = tid & 31;
    const int g    = lane >> 2, t = lane & 3;
    const int wm   = (wid & 3) * 32;
    const int wn   = (wid >> 2) * 64;

    const uint32_t AsA = smem_u32(As);
    const uint32_t BsA = smem_u32(Bs);
    const int lm_r = ((lane >> 3) & 1) * 8 + (lane & 7);
    const int lm_c = (lane >> 4) * 4;

    const int lrow = tid >> 3;
    const int lc4  = tid & 7;
    const float* pA = Ap + (size_t)(m0 + lrow) * K + lc4 * 4;
    const float* pB = W  + (size_t)(n0 + lrow) * K + lc4 * 4;

    float acc[2][8][4];
#pragma unroll
    for (int i = 0; i < 2; i++)
#pragma unroll
        for (int j = 0; j < 8; j++)
#pragma unroll
            for (int l = 0; l < 4; l++) acc[i][j][l] = 0.f;

    float4 ra[4], rb[4];
#pragma unroll
    for (int i = 0; i < 4; i++) {
        ra[i] = *(const float4*)(pA + (size_t)(32 * i) * K);
        rb[i] = *(const float4*)(pB + (size_t)(32 * i) * K);
    }

    for (int kb = 0; kb < K / 32; kb++) {
#pragma unroll
        for (int i = 0; i < 4; i++) {
            *(uint2*)&As[(lrow + 32 * i) * GLD + lc4 * 2] =
                make_uint2(f2h2(ra[i].x, ra[i].y), f2h2(ra[i].z, ra[i].w));
            *(uint2*)&Bs[(lrow + 32 * i) * GLD + lc4 * 2] =
                make_uint2(f2h2(rb[i].x, rb[i].y), f2h2(rb[i].z, rb[i].w));
        }
        __syncthreads();

        if (kb + 1 < K / 32) {
#pragma unroll
            for (int i = 0; i < 4; i++) {
                ra[i] = *(const float4*)(pA + (size_t)(32 * i) * K + (kb + 1) * 32);
                rb[i] = *(const float4*)(pB + (size_t)(32 * i) * K + (kb + 1) * 32);
            }
        }

#pragma unroll
        for (int kt = 0; kt < 2; kt++) {
            const int kq = kt * 8;
            uint32_t af[2][4];
#pragma unroll
            for (int mt = 0; mt < 2; mt++)
                LDSM_X4(af[mt][0], af[mt][1], af[mt][2], af[mt][3],
                        AsA + 4 * ((wm + mt * 16 + lm_r) * GLD + kq + lm_c));
            uint32_t bf[8][2];
#pragma unroll
            for (int p = 0; p < 4; p++) {
                uint32_t r0, r1, r2, r3;
                LDSM_X4(r0, r1, r2, r3,
                        BsA + 4 * ((wn + p * 16 + lm_r) * GLD + kq + lm_c));
                bf[2 * p][0] = r0; bf[2 * p + 1][0] = r1;
                bf[2 * p][1] = r2; bf[2 * p + 1][1] = r3;
            }
#pragma unroll
            for (int nt = 0; nt < 8; nt++)
#pragma unroll
                for (int mt = 0; mt < 2; mt++)
                    MMA_F16(acc[mt][nt], af[mt][0], af[mt][1], af[mt][2], af[mt][3],
                            bf[nt][0], bf[nt][1]);
        }
        __syncthreads();
    }

    // Q projection folds 0.125 * log2(e): scores become ex2-ready exponents
    const float osc = (MODE == 1) ? 0.125f * 1.4426950408889634f : 1.0f;
#pragma unroll
    for (int nt = 0; nt < 8; nt++) {
        const int n = n0 + wn + nt * 8 + 2 * t;
        const float b0 = bias[n], b1 = bias[n + 1];
#pragma unroll
        for (int mt = 0; mt < 2; mt++) {
            const int mlo = m0 + wm + mt * 16 + g;
            const int mhi = mlo + 8;
            const float v00 = (acc[mt][nt][0] + b0) * osc, v01 = (acc[mt][nt][1] + b1) * osc;
            const float v10 = (acc[mt][nt][2] + b0) * osc, v11 = (acc[mt][nt][3] + b1) * osc;
            if (MODE == 0) {
                *(float2*)(C + (size_t)mlo * EMB + n) = make_float2(v00, v01);
                *(float2*)(C + (size_t)mhi * EMB + n) = make_float2(v10, v11);
            } else {
                const int h = n >> 6, dd = n & 63;
                uint32_t* dst = (MODE == 1) ? g_Qh16 : (MODE == 2 ? g_Kh16 : g_Vh16);
                const int blo = mlo / SQ, slo = mlo % SQ;
                const int bhi = mhi / SQ, shi = mhi % SQ;
                dst[((size_t)(blo * HN + h) * SQ + slo) * 32 + (dd >> 1)] = f2h2(v00, v01);
                dst[((size_t)(bhi * HN + h) * SQ + shi) * 32 + (dd >> 1)] = f2h2(v10, v11);
            }
        }
    }
}

// Fused QKV projection: blockIdx.z selects {Q,K,V}. One launch, 768 CTAs.
__global__ void __launch_bounds__(256, 2) qkv_mma(const float* __restrict__ Xq,
                                                  const float* __restrict__ Xk,
                                                  const float* __restrict__ Xv,
                                                  const float* __restrict__ Wq,
                                                  const float* __restrict__ Wk,
                                                  const float* __restrict__ Wv,
                                                  const float* __restrict__ bq,
                                                  const float* __restrict__ bk,
                                                  const float* __restrict__ bv)
{
    __shared__ uint32_t As[128 * GLD];
    __shared__ uint32_t Bs[128 * GLD];
    const int m0 = blockIdx.y * 128, n0 = blockIdx.x * 128;
    const int z = blockIdx.z;
    if (z == 0)      gemm_body<1>(Xq, Wq, bq, nullptr, As, Bs, m0, n0);
    else if (z == 1) gemm_body<2>(Xk, Wk, bk, nullptr, As, Bs, m0, n0);
    else             gemm_body<3>(Xv, Wv, bv, nullptr, As, Bs, m0, n0);
}

// Output projection
__global__ void __launch_bounds__(256, 2) oproj_mma(const float* __restrict__ W,
                                                    const float* __restrict__ bias,
                                                    float* __restrict__ C)
{
    __shared__ uint32_t As[128 * GLD];
    __shared__ uint32_t Bs[128 * GLD];
    gemm_body<0>(g_ctx, W, bias, C, As, Bs, blockIdx.y * 128, blockIdx.x * 128);
}

// ===========================================================================
// Fully fused attention (R15 structure): scores + no-max softmax + PV.
// attn written with st.global.cs (write-once, never re-read) to preserve
// K/V L2 residency for the cp.async pipelines.
// ===========================================================================
#define FS_LD  36
#define FS_TILE (128 * FS_LD)
#define FUSED_SMEM (5 * FS_TILE * 4)  // Q + 2xK + 2xV = 92160 B

__global__ void __launch_bounds__(256, 2) fused_attn(float* __restrict__ attn)
{
    const int bh = blockIdx.y;
    const int b = bh >> 4, h = bh & 15;
    const int bm = (int)gridDim.x - 1 - (int)blockIdx.x;  // heavy tiles first
    float* out = attn + (size_t)bh * SQ * SQ;
    const uint32_t* Q16 = g_Qh16 + (size_t)bh * SQ * 32;
    const uint32_t* K16 = g_Kh16 + (size_t)bh * SQ * 32;
    const uint32_t* V16 = g_Vh16 + (size_t)bh * SQ * 32;

    extern __shared__ __align__(16) uint32_t dyn_smem[];
    const uint32_t QsA = smem_u32(dyn_smem);
    const uint32_t KsA = QsA + FS_TILE * 4;          // K stages 0,1
    const uint32_t VsA = QsA + 3 * FS_TILE * 4;      // V stages (pass0: K stage 2)

    const int tid = threadIdx.x;
    const int wid = tid >> 5, lane = tid & 31;
    const int g = lane >> 2, t = lane & 3;
    const int wm = wid * 16;
    const int lm_r = ((lane >> 3) & 1) * 8 + (lane & 7);
    const int lm_c = (lane >> 4) * 4;
    const int lm_v = lane >> 4;

    const int lrow = tid >> 3;
    const int lc4  = tid & 7;

    auto kstage = [&](int s) -> uint32_t {
        return (s < 2) ? (KsA + (uint32_t)s * FS_TILE * 4) : VsA;
    };

    // ---- prologue: Q tile, K0, K1 ----
#pragma unroll
    for (int i = 0; i < 4; i++) {
        const int row = lrow + 32 * i;
        CP_ASYNC16(QsA + (row * FS_LD + lc4 * 4) * 4,
                   Q16 + (size_t)(bm * 128 + row) * 32 + lc4 * 4);
    }
    CP_COMMIT();
#pragma unroll
    for (int i = 0; i < 4; i++) {
        const int row = lrow + 32 * i;
        CP_ASYNC16(kstage(0) + (row * FS_LD + lc4 * 4) * 4,
                   K16 + (size_t)row * 32 + lc4 * 4);
    }
    CP_COMMIT();
    if (bm >= 1) {
#pragma unroll
        for (int i = 0; i < 4; i++) {
            const int row = lrow + 32 * i;
            CP_ASYNC16(kstage(1) + (row * FS_LD + lc4 * 4) * 4,
                       K16 + (size_t)(128 + row) * 32 + lc4 * 4);
        }
        CP_COMMIT();
    }

    const int R0 = bm * 128 + wm + g;
    const int R1 = R0 + 8;

    uint32_t af[4][4];

    // ================= Pass 0: row sums of 2^y, single sync per kb ======
    float s0 = 0.f, s1 = 0.f;

    for (int kb = 0; kb <= bm; kb++) {
        if (kb < bm) { CP_WAIT1(); } else { CP_WAIT0(); }
        __syncthreads();

        if (kb == 0) {
#pragma unroll
            for (int kt = 0; kt < 4; kt++)
                LDSM_X4(af[kt][0], af[kt][1], af[kt][2], af[kt][3],
                        QsA + 4 * ((wm + lm_r) * FS_LD + kt * 8 + lm_c));
        }

        const uint32_t KsbA = kstage(kb % 3);
        const bool diag = (kb == bm);
        const int jjmax = diag ? (wid + 1) : 8;  // strips jj>wid fully masked
#pragma unroll
        for (int jj = 0; jj < 8; jj++) {
            if (jj >= jjmax) break;
            float p0[4] = {0.f, 0.f, 0.f, 0.f};
            float p1[4] = {0.f, 0.f, 0.f, 0.f};
#pragma unroll
            for (int kt = 0; kt < 4; kt++) {
                uint32_t r0, r1, r2, r3;
                LDSM_X4(r0, r1, r2, r3,
                        KsbA + 4 * ((jj * 16 + lm_r) * FS_LD + kt * 8 + lm_c));
                MMA_F16(p0, af[kt][0], af[kt][1], af[kt][2], af[kt][3], r0, r2);
                MMA_F16(p1, af[kt][0], af[kt][1], af[kt][2], af[kt][3], r1, r3);
            }
            float x00 = p0[0], x01 = p0[1];
            float x10 = p1[0], x11 = p1[1];
            float x02 = p0[2], x03 = p0[3];
            float x12 = p1[2], x13 = p1[3];
            if (diag) {
                const int c = kb * 128 + jj * 16 + 2 * t;
                if (c     > R0) x00 = -INFINITY;
                if (c + 1 > R0) x01 = -INFINITY;
                if (c + 8 > R0) x10 = -INFINITY;
                if (c + 9 > R0) x11 = -INFINITY;
                if (c     > R1) x02 = -INFINITY;
                if (c + 1 > R1) x03 = -INFINITY;
                if (c + 8 > R1) x12 = -INFINITY;
                if (c + 9 > R1) x13 = -INFINITY;
            }
            s0 += ex2f(x00) + ex2f(x01) + ex2f(x10) + ex2f(x11);
            s1 += ex2f(x02) + ex2f(x03) + ex2f(x12) + ex2f(x13);
        }

        if (kb + 2 <= bm) {
            const uint32_t dstA = kstage((kb + 2) % 3);
#pragma unroll
            for (int i = 0; i < 4; i++) {
                const int row = lrow + 32 * i;
                CP_ASYNC16(dstA + (row * FS_LD + lc4 * 4) * 4,
                           K16 + (size_t)((kb + 2) * 128 + row) * 32 + lc4 * 4);
            }
            CP_COMMIT();
        }
    }
    __syncthreads();  // protect pass-1 prologue writes

    s0 += __shfl_xor_sync(0xffffffffu, s0, 1);
    s0 += __shfl_xor_sync(0xffffffffu, s0, 2);
    s1 += __shfl_xor_sync(0xffffffffu, s1, 1);
    s1 += __shfl_xor_sync(0xffffffffu, s1, 2);
    const float inv0 = 1.f / s0;
    const float inv1 = 1.f / s1;

    // ================= Pass 1: recompute + write attn + O accum =========
    float o_acc[8][4];
#pragma unroll
    for (int dt = 0; dt < 8; dt++)
#pragma unroll
        for (int l = 0; l < 4; l++) o_acc[dt][l] = 0.f;

    float* rowlo = out + (size_t)R0 * SQ;
    float* rowhi = out + (size_t)R1 * SQ;

#pragma unroll
    for (int i = 0; i < 4; i++) {
        const int row = lrow + 32 * i;
        CP_ASYNC16(KsA + (row * FS_LD + lc4 * 4) * 4,
                   K16 + (size_t)row * 32 + lc4 * 4);
        CP_ASYNC16(VsA + (row * FS_LD + lc4 * 4) * 4,
                   V16 + (size_t)row * 32 + lc4 * 4);
    }
    CP_COMMIT();

    for (int kb = 0; kb <= bm; kb++) {
        if (kb < bm) {
            const uint32_t dstK = KsA + ((kb + 1) & 1) * FS_TILE * 4;
            const uint32_t dstV = VsA + ((kb + 1) & 1) * FS_TILE * 4;
#pragma unroll
            for (int i = 0; i < 4; i++) {
                const int row = lrow + 32 * i;
                CP_ASYNC16(dstK + (row * FS_LD + lc4 * 4) * 4,
                           K16 + (size_t)((kb + 1) * 128 + row) * 32 + lc4 * 4);
                CP_ASYNC16(dstV + (row * FS_LD + lc4 * 4) * 4,
                           V16 + (size_t)((kb + 1) * 128 + row) * 32 + lc4 * 4);
            }
            CP_COMMIT();
            CP_WAIT1();
        } else {
            CP_WAIT0();
        }
        __syncthreads();

        const uint32_t KsbA = KsA + (kb & 1) * FS_TILE * 4;
        const uint32_t VsbA = VsA + (kb & 1) * FS_TILE * 4;
        const bool diag = (kb == bm);
        const int jjmax = diag ? (wid + 1) : 8;
#pragma unroll
        for (int jj = 0; jj < 8; jj++) {
            if (jj >= jjmax) break;
            float p0[4] = {0.f, 0.f, 0.f, 0.f};
            float p1[4] = {0.f, 0.f, 0.f, 0.f};
#pragma unroll
            for (int kt = 0; kt < 4; kt++) {
                uint32_t r0, r1, r2, r3;
                LDSM_X4(r0, r1, r2, r3,
                        KsbA + 4 * ((jj * 16 + lm_r) * FS_LD + kt * 8 + lm_c));
                MMA_F16(p0, af[kt][0], af[kt][1], af[kt][2], af[kt][3], r0, r2);
                MMA_F16(p1, af[kt][0], af[kt][1], af[kt][2], af[kt][3], r1, r3);
            }
            float x00 = p0[0], x01 = p0[1];
            float x10 = p1[0], x11 = p1[1];
            float x02 = p0[2], x03 = p0[3];
            float x12 = p1[2], x13 = p1[3];
            const int c = kb * 128 + jj * 16 + 2 * t;
            if (diag) {
                if (c     > R0) x00 = -INFINITY;
                if (c + 1 > R0) x01 = -INFINITY;
                if (c + 8 > R0) x10 = -INFINITY;
                if (c + 9 > R0) x11 = -INFINITY;
                if (c     > R1) x02 = -INFINITY;
                if (c + 1 > R1) x03 = -INFINITY;
                if (c + 8 > R1) x12 = -INFINITY;
                if (c + 9 > R1) x13 = -INFINITY;
            }
            const float e00 = ex2f(x00) * inv0;  // masked -> exact 0
            const float e01 = ex2f(x01) * inv0;
            const float e10 = ex2f(x10) * inv0;
            const float e11 = ex2f(x11) * inv0;
            const float e02 = ex2f(x02) * inv1;
            const float e03 = ex2f(x03) * inv1;
            const float e12 = ex2f(x12) * inv1;
            const float e13 = ex2f(x13) * inv1;

            stg_cs_v2(rowlo + c,     e00, e01);
            stg_cs_v2(rowlo + c + 8, e10, e11);
            stg_cs_v2(rowhi + c,     e02, e03);
            stg_cs_v2(rowhi + c + 8, e12, e13);

            const uint32_t pa0 = f2h2(e00, e01);
            const uint32_t pa1 = f2h2(e02, e03);
            const uint32_t pa2 = f2h2(e10, e11);
            const uint32_t pa3 = f2h2(e12, e13);
#pragma unroll
            for (int p = 0; p < 4; p++) {
                uint32_t r0, r1, r2, r3;
                LDSM_X4_T(r0, r1, r2, r3,
                          VsbA + 4 * ((jj * 16 + lm_r) * FS_LD + (2 * p + lm_v) * 4));
                MMA_F16(o_acc[2 * p],     pa0, pa1, pa2, pa3, r0, r1);
                MMA_F16(o_acc[2 * p + 1], pa0, pa1, pa2, pa3, r2, r3);
            }
        }

        if (diag) {  // zero-fill skipped strips
            for (int jj = jjmax; jj < 8; jj++) {
                const int c = kb * 128 + jj * 16 + 2 * t;
                stg_cs_v2(rowlo + c,     0.f, 0.f);
                stg_cs_v2(rowlo + c + 8, 0.f, 0.f);
                stg_cs_v2(rowhi + c,     0.f, 0.f);
                stg_cs_v2(rowhi + c + 8, 0.f, 0.f);
            }
        }
        __syncthreads();
    }

    // ---- O epilogue ----
    float* olo = g_ctx + ((size_t)(b * SQ + R0)) * EMB + h * DH;
    float* ohi = g_ctx + ((size_t)(b * SQ + R1)) * EMB + h * DH;
#pragma unroll
    for (int dt = 0; dt < 8; dt++) {
        const int c = dt * 8 + 2 * t;
        *(float2*)(olo + c) = make_float2(o_acc[dt][0], o_acc[dt][1]);
        *(float2*)(ohi + c) = make_float2(o_acc[dt][2], o_acc[dt][3]);
    }

    // ---- zero-fill upper triangle beyond the diag tile (streaming) ----
    const int cstart = (bm + 1) * 128;
    const int nc4 = (SQ - cstart) >> 2;
    for (int idx = tid; idx < 128 * nc4; idx += 256) {
        const int r = idx / nc4, cc = idx - r * nc4;
        stg_cs_v4_zero(out + (size_t)(bm * 128 + r) * SQ + cstart + cc * 4);
    }
}

// ---------------------------------------------------------------------------
extern "C" void kernel_launch(void* const* d_in, const int* in_sizes, int n_in,
                              void* d_out, int out_size)
{
    const float* query = (const float*)d_in[0];
    const float* key_  = (const float*)d_in[1];
    const float* value = (const float*)d_in[2];
    const float* Wq = (const float*)d_in[3];
    const float* bq = (const float*)d_in[4];
    const float* Wk = (const float*)d_in[5];
    const float* bk = (const float*)d_in[6];
    const float* Wv = (const float*)d_in[7];
    const float* bv = (const float*)d_in[8];
    const float* Wo = (const float*)d_in[9];
    const float* bo = (const float*)d_in[10];

    const long long OUT_E = (long long)BSZ * SQ * EMB;
    const long long ATT_E = (long long)BH * SQ * SQ;

    float* outp = (float*)d_out;
    float* attn;
    if ((long long)out_size >= OUT_E + ATT_E) {
        attn = outp + OUT_E;
    } else {
        void* p = nullptr;
        cudaGetSymbolAddress(&p, g_attn_fb);
        attn = (float*)p;
    }

    cudaFuncSetAttribute(fused_attn, cudaFuncAttributeMaxDynamicSharedMemorySize,
                         FUSED_SMEM);

    dim3 gqkv(EMB / 128, (BSZ * SQ) / 128, 3);  // (8, 32, 3) = 768 CTAs
    qkv_mma<<<gqkv, 256>>>(query, key_, value, Wq, Wk, Wv, bq, bk, bv);

    dim3 gfs(SQ / 128, BH);                     // (16, 32)
    fused_attn<<<gfs, 256, FUSED_SMEM>>>(attn);

    dim3 gout(EMB / 128, (BSZ * SQ) / 128);     // (8, 32)
    oproj_mma<<<gout, 256>>>(Wo, bo, outp);
}